// round 4
// baseline (speedup 1.0000x reference)
#include <cuda_runtime.h>
#include <math.h>

#define C 128
#define H 256
#define W 256
#define HW (H*W)
#define RB 8            // reduction partials per channel

// ---------------- scratch (no allocations allowed) ----------------
__device__ float g_ps[C * RB];    // partial sums
__device__ float g_pss[C * RB];   // partial sums of squares
__device__ float g_WX[W][4];      // bicubic row-stochastic weight rows (h==w so shared)

// ---------------- bicubic helpers (PyTorch a=-0.75 kernel) ----------------
__device__ __forceinline__ float cubicw(float t) {
    float at = fabsf(t);
    float nearv = (1.25f * at - 2.25f) * at * at + 1.0f;
    float farv  = (((at - 5.0f) * at + 8.0f) * at - 4.0f) * -0.75f;
    return (at <= 1.0f) ? nearv : ((at < 2.0f) ? farv : 0.0f);
}

// Effective row o (crop-folded) of the clamped scatter-add (out,4) weight matrix.
__device__ __forceinline__ void wrow(int o, float wf[4]) {
    float src = ((float)(o + H / 2) + 0.5f) * (4.0f / (3.0f * (float)H)) - 0.5f;
    float fi0 = floorf(src);
    float t = src - fi0;
    int i0 = (int)fi0;
    wf[0] = wf[1] = wf[2] = wf[3] = 0.f;
#pragma unroll
    for (int j = 0; j < 4; ++j) {
        float wv = cubicw(t - (float)(j - 1));
        int idx = min(max(i0 + (j - 1), 0), 3);
        wf[idx] += wv;
    }
}

// ---------------- kernel A: partial sums over pre half + WX table ----------------
__global__ __launch_bounds__(256) void reduce_kernel(const float* __restrict__ x) {
    int b = blockIdx.x;              // 0..C*RB-1
    int c = b >> 3, part = b & (RB - 1);
    int t = threadIdx.x;

    // data-independent bicubic table, piggybacked on block 0
    if (b == 0) {
        float wf[4];
        wrow(t, wf);
        ((float4*)g_WX)[t] = make_float4(wf[0], wf[1], wf[2], wf[3]);
    }

    const float4* p = (const float4*)(x + (size_t)(C + c) * HW) + part * (HW / 4 / RB);
    float s = 0.f, ss = 0.f;
#pragma unroll
    for (int k = 0; k < HW / 4 / RB / 256; ++k) {   // 8 float4 per thread
        float4 v = __ldcs(&p[t + k * 256]);
        s  += v.x + v.y + v.z + v.w;
        ss += v.x * v.x + v.y * v.y + v.z * v.z + v.w * v.w;
    }
    __shared__ float sh_s[8], sh_ss[8];
#pragma unroll
    for (int off = 16; off; off >>= 1) {
        s  += __shfl_down_sync(0xFFFFFFFFu, s, off);
        ss += __shfl_down_sync(0xFFFFFFFFu, ss, off);
    }
    int wrp = t >> 5, lane = t & 31;
    if (lane == 0) { sh_s[wrp] = s; sh_ss[wrp] = ss; }
    __syncthreads();
    if (t == 0) {
        s = 0.f; ss = 0.f;
#pragma unroll
        for (int k = 0; k < 8; ++k) { s += sh_s[k]; ss += sh_ss[k]; }
        g_ps[b]  = s;
        g_pss[b] = ss;
    }
}

// ---------------- kernel B: finalize stats + patch + normalization ----------------
__global__ __launch_bounds__(256) void norm_kernel(
    const float* __restrict__ x, const float* __restrict__ mean_table,
    const float* __restrict__ std_table, const float* __restrict__ wt,
    const float* __restrict__ bs, const int* __restrict__ yap,
    const int* __restrict__ xap, const int* __restrict__ pyp,
    const int* __restrict__ pxp, float* __restrict__ out) {
    int c = blockIdx.y;
    int t = threadIdx.x;

    __shared__ float s_stat[3];      // mean, std, rstd of pre half (this channel)
    __shared__ float sm[16], si[16]; // 4x4 anchor patch: mean, 1/std

    if (t == 0) {
        float s = 0.f, ss = 0.f;
#pragma unroll
        for (int k = 0; k < RB; ++k) { s += g_ps[c * RB + k]; ss += g_pss[c * RB + k]; }
        float mean = s * (1.0f / (float)HW);
        float var  = fmaxf((ss - s * mean) * (1.0f / (float)(HW - 1)), 0.f);
        float sd   = sqrtf(var);
        s_stat[0] = mean; s_stat[1] = sd; s_stat[2] = 1.0f / sd;
    }
    __syncthreads();

    if (t < 16) {
        int ya = min(max(yap[0], 0), 15);   // dynamic_slice start clamp
        int xa = min(max(xap[0], 0), 15);
        int dy = t >> 2, dx = t & 3;
        int oy = min(max(ya + dy - 1, 0), 15);  // replication pad via clamp
        int ox = min(max(xa + dx - 1, 0), 15);
        float m, sd;
        if (oy == pyp[0] && ox == pxp[0]) { m = s_stat[0]; sd = s_stat[1]; }
        else {
            m  = mean_table[(oy * 16 + ox) * C + c];
            sd = std_table[(oy * 16 + ox) * C + c];
        }
        sm[t] = m;
        si[t] = 1.0f / sd;
    }
    __syncthreads();

    int o = blockIdx.x * 4 + (t >> 6);   // output row
    int q = t & 63;                      // float4 group within row

    size_t rbase = ((size_t)c * H + o) * W;
    const float4* xr = (const float4*)(x + rbase);
    const float4* xp = (const float4*)(x + rbase + (size_t)C * HW);
    float4* outr = (float4*)(out + rbase);
    float4* outp = (float4*)(out + rbase + (size_t)C * HW);

    // issue the big loads first (latency covers the weight math below)
    float4 vr = __ldcs(&xr[q]);
    float4 vp = __ldcs(&xp[q]);

    // per-row Y-contraction of the patch (redundant across the 64 row threads; cheap)
    float wf[4];
    wrow(o, wf);
    float ay[4], by[4];
#pragma unroll
    for (int xx = 0; xx < 4; ++xx) {
        float a = 0.f, b = 0.f;
#pragma unroll
        for (int y = 0; y < 4; ++y) {
            a = fmaf(wf[y], sm[y * 4 + xx], a);
            b = fmaf(wf[y], si[y * 4 + xx], b);
        }
        ay[xx] = a; by[xx] = b;
    }

    float wc = wt[c], bc = bs[c];
    float ps = s_stat[2] * wc;                 // pre-half fused scale
    float po = fmaf(-s_stat[0], ps, bc);       // pre-half fused offset

    float inr[4] = {vr.x, vr.y, vr.z, vr.w};
    float inp[4] = {vp.x, vp.y, vp.z, vp.w};
    float orr[4], opp[4];

    const float4* WX = (const float4*)g_WX;
#pragma unroll
    for (int j = 0; j < 4; ++j) {
        float4 w = WX[4 * q + j];              // pixel p = 4q+j
        float mean = w.x * ay[0] + w.y * ay[1] + w.z * ay[2] + w.w * ay[3];
        float inv  = w.x * by[0] + w.y * by[1] + w.z * by[2] + w.w * by[3];
        orr[j] = fmaf((inr[j] - mean) * inv, wc, bc);
        opp[j] = fmaf(inp[j], ps, po);
    }
    __stcs(&outr[q], make_float4(orr[0], orr[1], orr[2], orr[3]));
    __stcs(&outp[q], make_float4(opp[0], opp[1], opp[2], opp[3]));
}

// ---------------- launch ----------------
extern "C" void kernel_launch(void* const* d_in, const int* in_sizes, int n_in,
                              void* d_out, int out_size) {
    const float* x          = (const float*)d_in[0];
    const float* mean_table = (const float*)d_in[1];
    const float* std_table  = (const float*)d_in[2];
    const float* weight     = (const float*)d_in[3];
    const float* bias       = (const float*)d_in[4];
    const int*   y_anchor   = (const int*)d_in[5];
    const int*   x_anchor   = (const int*)d_in[6];
    const int*   pre_y1     = (const int*)d_in[7];
    const int*   pre_x1     = (const int*)d_in[8];
    float* out = (float*)d_out;

    reduce_kernel<<<C * RB, 256>>>(x);
    norm_kernel<<<dim3(H / 4, C), 256>>>(x, mean_table, std_table, weight, bias,
                                         y_anchor, x_anchor, pre_y1, pre_x1, out);
}